// round 14
// baseline (speedup 1.0000x reference)
#include <cuda_runtime.h>
#include <cuda_bf16.h>
#include <cuda_fp16.h>
#include <math.h>
#include <stdint.h>

#define L_DIM 2048
#define S_DIM 2048
#define N_B   4
#define E_DIM 256
#define H_N   8
#define HD_N  32
#define NH_N  32
#define SCALING 0.17677669529663687f

__device__ __align__(128) uint8_t g_qb[(size_t)NH_N * L_DIM * 128];
__device__ __align__(128) uint8_t g_kb[(size_t)NH_N * S_DIM * 128];
__device__ __align__(128) uint8_t g_vb[(size_t)NH_N * S_DIM * 128];
__device__ __align__(128) uint8_t g_wsp[(size_t)4 * 256 * 1024];
__device__ __align__(128) uint8_t g_ao[(size_t)8192 * 1024];

// ---------------- helpers ----------------
__device__ __forceinline__ uint32_t smem_u32(const void* p) {
    uint32_t a;
    asm("{ .reg .u64 t; cvta.to.shared.u64 t, %1; cvt.u32.u64 %0, t; }" : "=r"(a) : "l"(p));
    return a;
}
__device__ __forceinline__ uint32_t packh2(float a, float b) {
    __half2 t = __floats2half2_rn(a, b);
    return *(uint32_t*)&t;
}
__device__ __forceinline__ void split1(float v, uint32_t& hi16, uint32_t& lo16) {
    __nv_bfloat16 h = __float2bfloat16(v);
    __nv_bfloat16 l = __float2bfloat16(v - __bfloat162float(h));
    hi16 = __bfloat16_as_ushort(h);
    lo16 = __bfloat16_as_ushort(l);
}
__device__ __forceinline__ void split1h(float v, uint32_t& hi16, uint32_t& lo16) {
    __half h = __float2half_rn(v);
    __half l = __float2half_rn(v - __half2float(h));
    hi16 = __half_as_ushort(h);
    lo16 = __half_as_ushort(l);
}

#define LDSM4(R, addr)                                                          \
    asm volatile("ldmatrix.sync.aligned.m8n8.x4.shared.b16 {%0,%1,%2,%3}, [%4];" \
        : "=r"((R)[0]), "=r"((R)[1]), "=r"((R)[2]), "=r"((R)[3]) : "r"(addr))
#define LDSM4T(R, addr)                                                         \
    asm volatile("ldmatrix.sync.aligned.m8n8.x4.trans.shared.b16 {%0,%1,%2,%3}, [%4];" \
        : "=r"((R)[0]), "=r"((R)[1]), "=r"((R)[2]), "=r"((R)[3]) : "r"(addr))
#define CP16(dst, src)                                                          \
    asm volatile("cp.async.cg.shared.global [%0], [%1], 16;" :: "r"(dst), "l"(src))
#define CP_COMMIT() asm volatile("cp.async.commit_group;")
#define CP_WAIT0()  asm volatile("cp.async.wait_group 0;")
#define CP_WAIT1()  asm volatile("cp.async.wait_group 1;")

__device__ __forceinline__ void mma16816(float c[4], const uint32_t a[4],
                                         uint32_t b0, uint32_t b1) {
    asm volatile("mma.sync.aligned.m16n8k16.row.col.f32.bf16.bf16.f32 "
        "{%0,%1,%2,%3}, {%4,%5,%6,%7}, {%8,%9}, {%0,%1,%2,%3};"
        : "+f"(c[0]), "+f"(c[1]), "+f"(c[2]), "+f"(c[3])
        : "r"(a[0]), "r"(a[1]), "r"(a[2]), "r"(a[3]), "r"(b0), "r"(b1));
}
__device__ __forceinline__ void mma16816h(float c[4], const uint32_t a[4],
                                          uint32_t b0, uint32_t b1) {
    asm volatile("mma.sync.aligned.m16n8k16.row.col.f32.f16.f16.f32 "
        "{%0,%1,%2,%3}, {%4,%5,%6,%7}, {%8,%9}, {%0,%1,%2,%3};"
        : "+f"(c[0]), "+f"(c[1]), "+f"(c[2]), "+f"(c[3])
        : "r"(a[0]), "r"(a[1]), "r"(a[2]), "r"(a[3]), "r"(b0), "r"(b1));
}

// ---------------- weight conversion (once; tiny) ----------------
__global__ __launch_bounds__(256)
void convert_w_kernel(const float* __restrict__ ipw, const float* __restrict__ opw)
{
    const int z = blockIdx.y;
    const float* src = (z < 3) ? (ipw + (size_t)z * 65536) : opw;
    uint8_t* dst = g_wsp + (size_t)z * 262144;
    size_t g = ((size_t)blockIdx.x * 256 + threadIdx.x) * 4;
    float4 v = *(const float4*)(src + g);
    uint32_t h0,l0,h1,l1,h2,l2,h3,l3;
    split1(v.x,h0,l0); split1(v.y,h1,l1); split1(v.z,h2,l2); split1(v.w,h3,l3);
    size_t row = g >> 8;
    int c = (int)(g & 255);
    uint8_t* rp = dst + row * 1024;
    *(uint2*)(rp + 2*c)       = make_uint2(h0 | (h1<<16), h2 | (h3<<16));
    *(uint2*)(rp + 512 + 2*c) = make_uint2(l0 | (l1<<16), l2 | (l3<<16));
}

// ---------------- HMMA projection GEMM ----------------
#define PPITCH 144

__global__ __launch_bounds__(128)
void proj_mma_kernel(const float* __restrict__ q_in, const float* __restrict__ k_in,
                     const float* __restrict__ v_in,
                     const float* __restrict__ ipb, const float* __restrict__ opb,
                     float* __restrict__ out, int mode)
{
    __shared__ __align__(16) uint8_t sA[64 * PPITCH];
    __shared__ __align__(16) uint8_t sW[128 * PPITCH];

    const int tid  = threadIdx.x;
    const int wid  = tid >> 5;
    const int lane = tid & 31;
    const int z = blockIdx.z;
    const int m0 = blockIdx.x * 64;
    const int n0 = blockIdx.y * 128;
    const int wm = wid >> 1;
    const int wn = wid & 1;

    const float* Af = (z == 0) ? q_in : (z == 1) ? k_in : v_in;
    const uint8_t* Wsp = g_wsp + (size_t)((mode == 0) ? z : 3) * 262144;
    const float* bias = (mode == 0) ? (ipb + z * E_DIM) : opb;
    const float scale = (mode == 0 && z == 0) ? SCALING : 1.0f;

    float acc[2][8][4];
#pragma unroll
    for (int a = 0; a < 2; a++)
#pragma unroll
        for (int t = 0; t < 8; t++)
#pragma unroll
            for (int j = 0; j < 4; j++) acc[a][t][j] = 0.f;

    const uint32_t sAb = smem_u32(sA), sWb = smem_u32(sW);

    for (int kc = 0; kc < 8; kc++) {
        const int koff = kc * 64;
        __syncthreads();
        if (mode == 0) {
#pragma unroll
            for (int j = 0; j < 4; j++) {
                int i = tid + j * 128;
                int row = i >> 3, seg = i & 7;
                float4 v = *(const float4*)(Af + (size_t)(m0 + row) * E_DIM
                                            + kc * 32 + seg * 4);
                uint32_t h0,l0,h1,l1,h2,l2,h3,l3;
                split1(v.x,h0,l0); split1(v.y,h1,l1);
                split1(v.z,h2,l2); split1(v.w,h3,l3);
                *(uint2*)(sA + row * PPITCH + seg * 8) =
                    make_uint2(h0 | (h1<<16), h2 | (h3<<16));
                *(uint2*)(sA + row * PPITCH + 64 + seg * 8) =
                    make_uint2(l0 | (l1<<16), l2 | (l3<<16));
            }
        } else {
#pragma unroll
            for (int j = 0; j < 4; j++) {
                int i = tid + j * 128;
                int row = i >> 3, seg = i & 7;
                const uint8_t* src = g_ao + (size_t)(m0 + row) * 1024
                                   + (seg < 4 ? koff + seg * 16 : 512 + koff + (seg - 4) * 16);
                uint8_t* dst = sA + row * PPITCH + (seg < 4 ? seg * 16 : 64 + (seg - 4) * 16);
                *(uint4*)dst = *(const uint4*)src;
            }
        }
#pragma unroll
        for (int j = 0; j < 8; j++) {
            int i = tid + j * 128;
            int row = i >> 3, seg = i & 7;
            const uint8_t* src = Wsp + (size_t)(n0 + row) * 1024
                               + (seg < 4 ? koff + seg * 16 : 512 + koff + (seg - 4) * 16);
            uint8_t* dst = sW + row * PPITCH + (seg < 4 ? seg * 16 : 64 + (seg - 4) * 16);
            *(uint4*)dst = *(const uint4*)src;
        }
        __syncthreads();

#pragma unroll
        for (int ks = 0; ks < 2; ks++) {
            uint32_t ah[2][4], al[2][4];
#pragma unroll
            for (int am = 0; am < 2; am++) {
                uint32_t aaddr = sAb + (wm*32 + am*16 + (lane & 15)) * PPITCH
                               + ks*32 + (lane >> 4) * 16;
                LDSM4(ah[am], aaddr);
                LDSM4(al[am], aaddr + 64);
            }
            uint32_t bh[4][4], bl[4][4];
#pragma unroll
            for (int g = 0; g < 4; g++) {
                uint32_t baddr = sWb + (wn*64 + g*16 + (lane & 7) + ((lane >> 4) << 3)) * PPITCH
                               + ks*32 + ((lane >> 3) & 1) * 16;
                LDSM4(bh[g], baddr);
                LDSM4(bl[g], baddr + 64);
            }
            // term-outermost: 16 independent accumulator chains per term round
            // (per-accumulator order unchanged: ah*bh, ah*bl, al*bh)
#pragma unroll
            for (int am = 0; am < 2; am++)
#pragma unroll
                for (int g = 0; g < 4; g++) {
                    mma16816(acc[am][2*g+0], ah[am], bh[g][0], bh[g][1]);
                    mma16816(acc[am][2*g+1], ah[am], bh[g][2], bh[g][3]);
                }
#pragma unroll
            for (int am = 0; am < 2; am++)
#pragma unroll
                for (int g = 0; g < 4; g++) {
                    mma16816(acc[am][2*g+0], ah[am], bl[g][0], bl[g][1]);
                    mma16816(acc[am][2*g+1], ah[am], bl[g][2], bl[g][3]);
                }
#pragma unroll
            for (int am = 0; am < 2; am++)
#pragma unroll
                for (int g = 0; g < 4; g++) {
                    mma16816(acc[am][2*g+0], al[am], bh[g][0], bh[g][1]);
                    mma16816(acc[am][2*g+1], al[am], bh[g][2], bh[g][3]);
                }
        }
    }

    const int qrow = lane >> 2, qcol = (lane & 3) << 1;
    uint8_t* dstz = (z == 0) ? g_qb : (z == 1) ? g_kb : g_vb;
#pragma unroll
    for (int am = 0; am < 2; am++) {
        const int r0 = m0 + wm*32 + am*16 + qrow;
#pragma unroll
        for (int t = 0; t < 8; t++) {
            const int e = n0 + wn*64 + (t >> 1)*16 + (t & 1)*8 + qcol;
            const float b0 = bias[e], b1 = bias[e+1];
            float v00 = (acc[am][t][0] + b0) * scale;
            float v01 = (acc[am][t][1] + b1) * scale;
            float v10 = (acc[am][t][2] + b0) * scale;
            float v11 = (acc[am][t][3] + b1) * scale;
            if (mode == 0) {
                const int hh = e >> 5, d = e & 31;
#pragma unroll
                for (int half = 0; half < 2; half++) {
                    const int r = r0 + half * 8;
                    const float va = half ? v10 : v00;
                    const float vb = half ? v11 : v01;
                    const int l = r >> 2, nn = r & 3;
                    uint8_t* rp = dstz + ((size_t)(nn * H_N + hh) * L_DIM + l) * 128;
                    uint32_t ha,la,hb,lb;
                    if (z == 2) { split1h(va, ha, la); split1h(vb, hb, lb); }
                    else        { split1(va, ha, la);  split1(vb, hb, lb); }
                    *(uint32_t*)(rp + 2*d)      = ha | (hb << 16);
                    *(uint32_t*)(rp + 64 + 2*d) = la | (lb << 16);
                }
            } else {
                *(float2*)(out + (size_t)r0 * E_DIM + e)       = make_float2(v00, v01);
                *(float2*)(out + (size_t)(r0+8) * E_DIM + e)   = make_float2(v10, v11);
            }
        }
    }
}

// ---------------- Attention: HMMA flash v5 (interleaved MMA chains) ----------------
#define KV_PITCH  144
#define REL_PITCH 36
#define SM_K(b)   ((b) * 4608)
#define SM_V(b)   (9216 + (b) * 4608)
#define SM_REL(b) (18432 + (b) * 18432)
#define SMEM_ATTN 55296

__global__ void __launch_bounds__(128, 4) attn_mma_kernel(const float* __restrict__ rel)
{
    extern __shared__ __align__(16) uint8_t smem[];
    const int tid  = threadIdx.x;
    const int wid  = tid >> 5;
    const int lane = tid & 31;
    const int bh = blockIdx.y;
    const int l0 = blockIdx.x * 128;
    const int WROW = wid * 32;

    const uint32_t sb = smem_u32(smem);
    const uint4* ksrc = (const uint4*)(g_kb + (size_t)bh * S_DIM * 128);
    const uint4* vsrc = (const uint4*)(g_vb + (size_t)bh * S_DIM * 128);
    const float* relg = rel + ((size_t)bh * L_DIM + l0) * S_DIM;

    {
        const uint4* qs = (const uint4*)(g_qb + ((size_t)bh * L_DIM + l0) * 128);
        uint32_t qb = sb + SM_REL(0);
#pragma unroll
        for (int j = 0; j < 8; j++) {
            int i = tid + j * 128;
            CP16(qb + (i >> 3) * KV_PITCH + (i & 7) * 16, qs + i);
        }
        CP_COMMIT(); CP_WAIT0();
    }
    __syncthreads();
    uint32_t qh0[2][4], qh1[2][4], ql0[2][4], ql1[2][4];
#pragma unroll
    for (int am = 0; am < 2; am++) {
        uint32_t qaddr = sb + SM_REL(0) + (WROW + 16*am + (lane & 15)) * KV_PITCH
                       + (lane >> 4) * 16;
        LDSM4(qh0[am], qaddr);
        LDSM4(qh1[am], qaddr + 32);
        LDSM4(ql0[am], qaddr + 64);
        LDSM4(ql1[am], qaddr + 96);
    }
    __syncthreads();

    {
#pragma unroll
        for (int j = 0; j < 2; j++) {
            int i = tid + j * 128;
            uint32_t o = (i >> 3) * KV_PITCH + (i & 7) * 16;
            CP16(sb + SM_K(0) + o, ksrc + i);
            CP16(sb + SM_V(0) + o, vsrc + i);
        }
#pragma unroll
        for (int j = 0; j < 8; j++) {
            int i = tid + j * 128;
            int row = i >> 3, seg = i & 7;
            CP16(sb + SM_REL(0) + row * (REL_PITCH * 4) + seg * 16,
                 (const uint4*)(relg + (size_t)row * S_DIM) + seg);
        }
        CP_COMMIT();
    }

    float O[2][4][4];
#pragma unroll
    for (int am = 0; am < 2; am++)
#pragma unroll
        for (int t = 0; t < 4; t++)
#pragma unroll
            for (int j = 0; j < 4; j++) O[am][t][j] = 0.f;
    float rs[2][2] = {{0.f, 0.f}, {0.f, 0.f}};

    const int qrow = lane >> 2;
    const int qcol = (lane & 3) << 1;

    for (int c = 0; c < S_DIM / 32; ++c) {
        const int cur = c & 1;
        if (c + 1 < S_DIM / 32) {
            const int nxt = cur ^ 1;
            const int s1 = (c + 1) * 32;
#pragma unroll
            for (int j = 0; j < 2; j++) {
                int i = tid + j * 128;
                uint32_t o = (i >> 3) * KV_PITCH + (i & 7) * 16;
                CP16(sb + SM_K(nxt) + o, ksrc + (c + 1) * 256 + i);
                CP16(sb + SM_V(nxt) + o, vsrc + (c + 1) * 256 + i);
            }
#pragma unroll
            for (int j = 0; j < 8; j++) {
                int i = tid + j * 128;
                int row = i >> 3, seg = i & 7;
                CP16(sb + SM_REL(nxt) + row * (REL_PITCH * 4) + seg * 16,
                     (const uint4*)(relg + (size_t)row * S_DIM + s1) + seg);
            }
            CP_COMMIT();
            CP_WAIT1();
        } else {
            CP_WAIT0();
        }
        __syncthreads();

        const float* srel = (const float*)(smem + SM_REL(cur));
        const uint32_t skb = sb + SM_K(cur), svb = sb + SM_V(cur);

#pragma unroll
        for (int np = 0; np < 2; np++) {
            uint32_t kaddr = skb + (16*np + (lane & 7) + ((lane >> 4) << 3)) * KV_PITCH
                           + ((lane >> 3) & 1) * 16;
            uint32_t kh0[4], kh1[4], kl0[4], kl1[4];
            LDSM4(kh0, kaddr);
            LDSM4(kh1, kaddr + 32);
            LDSM4(kl0, kaddr + 64);
            LDSM4(kl1, kaddr + 96);
            uint32_t vaddr = svb + (16*np + (lane & 15)) * KV_PITCH + (lane >> 4) * 16;
            uint32_t vh0[4], vh1[4], vl0[4], vl1[4];
            LDSM4T(vh0, vaddr);
            LDSM4T(vh1, vaddr + 32);
            LDSM4T(vl0, vaddr + 64);
            LDSM4T(vl1, vaddr + 96);

#pragma unroll
            for (int am = 0; am < 2; am++) {
                const float* r0 = srel + (WROW + 16*am + qrow) * REL_PITCH + 16*np + qcol;
                float cA[4], cB[4];
                {
                    float2 t0 = *(const float2*)(r0);
                    float2 t1 = *(const float2*)(r0 + 8 * REL_PITCH);
                    float2 t2 = *(const float2*)(r0 + 8);
                    float2 t3 = *(const float2*)(r0 + 8 * REL_PITCH + 8);
                    cA[0]=t0.x; cA[1]=t0.y; cA[2]=t1.x; cA[3]=t1.y;
                    cB[0]=t2.x; cB[1]=t2.y; cB[2]=t3.x; cB[3]=t3.y;
                }
                // QK: 3-term bf16 split, cA/cB chains interleaved (2-way ILP);
                // per-accumulator term order unchanged -> bit-identical.
                mma16816(cA, qh0[am], kh0[0], kh0[1]);
                mma16816(cB, qh0[am], kh0[2], kh0[3]);
                mma16816(cA, qh1[am], kh1[0], kh1[1]);
                mma16816(cB, qh1[am], kh1[2], kh1[3]);
                mma16816(cA, qh0[am], kl0[0], kl0[1]);
                mma16816(cB, qh0[am], kl0[2], kl0[3]);
                mma16816(cA, qh1[am], kl1[0], kl1[1]);
                mma16816(cB, qh1[am], kl1[2], kl1[3]);
                mma16816(cA, ql0[am], kh0[0], kh0[1]);
                mma16816(cB, ql0[am], kh0[2], kh0[3]);
                mma16816(cA, ql1[am], kh1[0], kh1[1]);
                mma16816(cB, ql1[am], kh1[2], kh1[3]);

                // exp + sums + fp16 pack
                float pA0 = __expf(cA[0]), pA1 = __expf(cA[1]);
                float pA2 = __expf(cA[2]), pA3 = __expf(cA[3]);
                float pB0 = __expf(cB[0]), pB1 = __expf(cB[1]);
                float pB2 = __expf(cB[2]), pB3 = __expf(cB[3]);
                rs[am][0] += (pA0 + pA1) + (pB0 + pB1);
                rs[am][1] += (pA2 + pA3) + (pB2 + pB3);

                uint32_t phi[4];
                phi[0] = packh2(pA0, pA1); phi[1] = packh2(pA2, pA3);
                phi[2] = packh2(pB0, pB1); phi[3] = packh2(pB2, pB3);

                // AV: 4 O-chains interleaved (hi round, then lo round);
                // per-accumulator order unchanged (hi then lo).
                mma16816h(O[am][0], phi, vh0[0], vh0[1]);
                mma16816h(O[am][1], phi, vh0[2], vh0[3]);
                mma16816h(O[am][2], phi, vh1[0], vh1[1]);
                mma16816h(O[am][3], phi, vh1[2], vh1[3]);
                mma16816h(O[am][0], phi, vl0[0], vl0[1]);
                mma16816h(O[am][1], phi, vl0[2], vl0[3]);
                mma16816h(O[am][2], phi, vl1[0], vl1[1]);
                mma16816h(O[am][3], phi, vl1[2], vl1[3]);
            }
        }
        __syncthreads();
    }

    // ---- epilogue ----
    const int n = bh >> 3, h = bh & 7;
#pragma unroll
    for (int am = 0; am < 2; am++) {
        float s0 = rs[am][0], s1 = rs[am][1];
        s0 += __shfl_xor_sync(0xffffffffu, s0, 1);
        s0 += __shfl_xor_sync(0xffffffffu, s0, 2);
        s1 += __shfl_xor_sync(0xffffffffu, s1, 1);
        s1 += __shfl_xor_sync(0xffffffffu, s1, 2);
        const float inv0 = 1.0f / s0, inv1 = 1.0f / s1;

        const int r = l0 + WROW + 16*am + qrow;
        uint8_t* rp0 = g_ao + ((size_t)r * N_B + n) * 1024;
        uint8_t* rp8 = rp0 + (size_t)8 * N_B * 1024;
#pragma unroll
        for (int t = 0; t < 4; t++) {
            const int e = h * HD_N + t * 8 + qcol;
            uint32_t ha, la, hb, lb;
            split1(O[am][t][0] * inv0, ha, la); split1(O[am][t][1] * inv0, hb, lb);
            *(uint32_t*)(rp0 + 2*e)       = ha | (hb << 16);
            *(uint32_t*)(rp0 + 512 + 2*e) = la | (lb << 16);
            split1(O[am][t][2] * inv1, ha, la); split1(O[am][t][3] * inv1, hb, lb);
            *(uint32_t*)(rp8 + 2*e)       = ha | (hb << 16);
            *(uint32_t*)(rp8 + 512 + 2*e) = la | (lb << 16);
        }
    }
}

// ---------------------------------------------------------------------------
extern "C" void kernel_launch(void* const* d_in, const int* in_sizes, int n_in,
                              void* d_out, int out_size)
{
    const float* query = (const float*)d_in[0];
    const float* key   = (const float*)d_in[1];
    const float* value = (const float*)d_in[2];
    const float* rel   = (const float*)d_in[3];
    const float* ipw   = (const float*)d_in[4];
    const float* ipb   = (const float*)d_in[5];
    const float* opw   = (const float*)d_in[6];
    const float* opb   = (const float*)d_in[7];
    float* out = (float*)d_out;

    cudaFuncSetAttribute(attn_mma_kernel,
                         cudaFuncAttributeMaxDynamicSharedMemorySize, SMEM_ATTN);

    convert_w_kernel<<<dim3(64, 4), 256>>>(ipw, opw);

    proj_mma_kernel<<<dim3(128, 2, 3), 128>>>(query, key, value, ipb, opb, out, 0);

    attn_mma_kernel<<<dim3(16, 32), 128, SMEM_ATTN>>>(rel);

    proj_mma_kernel<<<dim3(128, 2, 1), 128>>>(query, key, value, ipb, opb, out, 1);
}

// round 15
// speedup vs baseline: 1.0184x; 1.0184x over previous
#include <cuda_runtime.h>
#include <cuda_bf16.h>
#include <cuda_fp16.h>
#include <math.h>
#include <stdint.h>

#define L_DIM 2048
#define S_DIM 2048
#define N_B   4
#define E_DIM 256
#define H_N   8
#define HD_N  32
#define NH_N  32
#define SCALING 0.17677669529663687f

__device__ __align__(128) uint8_t g_qb[(size_t)NH_N * L_DIM * 128];
__device__ __align__(128) uint8_t g_kb[(size_t)NH_N * S_DIM * 128];
__device__ __align__(128) uint8_t g_vb[(size_t)NH_N * S_DIM * 128];
__device__ __align__(128) uint8_t g_wsp[(size_t)4 * 256 * 1024];
__device__ __align__(128) uint8_t g_ao[(size_t)8192 * 1024];

// ---------------- helpers ----------------
__device__ __forceinline__ uint32_t smem_u32(const void* p) {
    uint32_t a;
    asm("{ .reg .u64 t; cvta.to.shared.u64 t, %1; cvt.u32.u64 %0, t; }" : "=r"(a) : "l"(p));
    return a;
}
__device__ __forceinline__ uint32_t packh2(float a, float b) {
    __half2 t = __floats2half2_rn(a, b);
    return *(uint32_t*)&t;
}
__device__ __forceinline__ void split1(float v, uint32_t& hi16, uint32_t& lo16) {
    __nv_bfloat16 h = __float2bfloat16(v);
    __nv_bfloat16 l = __float2bfloat16(v - __bfloat162float(h));
    hi16 = __bfloat16_as_ushort(h);
    lo16 = __bfloat16_as_ushort(l);
}
__device__ __forceinline__ void split1h(float v, uint32_t& hi16, uint32_t& lo16) {
    __half h = __float2half_rn(v);
    __half l = __float2half_rn(v - __half2float(h));
    hi16 = __half_as_ushort(h);
    lo16 = __half_as_ushort(l);
}

#define LDSM4(R, addr)                                                          \
    asm volatile("ldmatrix.sync.aligned.m8n8.x4.shared.b16 {%0,%1,%2,%3}, [%4];" \
        : "=r"((R)[0]), "=r"((R)[1]), "=r"((R)[2]), "=r"((R)[3]) : "r"(addr))
#define LDSM4T(R, addr)                                                         \
    asm volatile("ldmatrix.sync.aligned.m8n8.x4.trans.shared.b16 {%0,%1,%2,%3}, [%4];" \
        : "=r"((R)[0]), "=r"((R)[1]), "=r"((R)[2]), "=r"((R)[3]) : "r"(addr))
#define CP16(dst, src)                                                          \
    asm volatile("cp.async.cg.shared.global [%0], [%1], 16;" :: "r"(dst), "l"(src))
#define CP_COMMIT() asm volatile("cp.async.commit_group;")
#define CP_WAIT0()  asm volatile("cp.async.wait_group 0;")
#define CP_WAIT1()  asm volatile("cp.async.wait_group 1;")

__device__ __forceinline__ void mma16816(float c[4], const uint32_t a[4],
                                         uint32_t b0, uint32_t b1) {
    asm volatile("mma.sync.aligned.m16n8k16.row.col.f32.bf16.bf16.f32 "
        "{%0,%1,%2,%3}, {%4,%5,%6,%7}, {%8,%9}, {%0,%1,%2,%3};"
        : "+f"(c[0]), "+f"(c[1]), "+f"(c[2]), "+f"(c[3])
        : "r"(a[0]), "r"(a[1]), "r"(a[2]), "r"(a[3]), "r"(b0), "r"(b1));
}
__device__ __forceinline__ void mma16816h(float c[4], const uint32_t a[4],
                                          uint32_t b0, uint32_t b1) {
    asm volatile("mma.sync.aligned.m16n8k16.row.col.f32.f16.f16.f32 "
        "{%0,%1,%2,%3}, {%4,%5,%6,%7}, {%8,%9}, {%0,%1,%2,%3};"
        : "+f"(c[0]), "+f"(c[1]), "+f"(c[2]), "+f"(c[3])
        : "r"(a[0]), "r"(a[1]), "r"(a[2]), "r"(a[3]), "r"(b0), "r"(b1));
}

// ---------------- weight conversion (once; tiny) ----------------
__global__ __launch_bounds__(256)
void convert_w_kernel(const float* __restrict__ ipw, const float* __restrict__ opw)
{
    const int z = blockIdx.y;
    const float* src = (z < 3) ? (ipw + (size_t)z * 65536) : opw;
    uint8_t* dst = g_wsp + (size_t)z * 262144;
    size_t g = ((size_t)blockIdx.x * 256 + threadIdx.x) * 4;
    float4 v = *(const float4*)(src + g);
    uint32_t h0,l0,h1,l1,h2,l2,h3,l3;
    split1(v.x,h0,l0); split1(v.y,h1,l1); split1(v.z,h2,l2); split1(v.w,h3,l3);
    size_t row = g >> 8;
    int c = (int)(g & 255);
    uint8_t* rp = dst + row * 1024;
    *(uint2*)(rp + 2*c)       = make_uint2(h0 | (h1<<16), h2 | (h3<<16));
    *(uint2*)(rp + 512 + 2*c) = make_uint2(l0 | (l1<<16), l2 | (l3<<16));
}

// ---------------- HMMA projection GEMM, 64m x 64n tiles ----------------
// warp tile 32m x 32n (2x2 warps). acc[2][4][4] = 32 regs.
// mode 0 (QKV): A = fp32 input split on staging; epilogue split-scatter.
// mode 1 (out): A = g_ao raw copy; fp32 out.
#define PPITCH 144

__global__ __launch_bounds__(128)
void proj_mma_kernel(const float* __restrict__ q_in, const float* __restrict__ k_in,
                     const float* __restrict__ v_in,
                     const float* __restrict__ ipb, const float* __restrict__ opb,
                     float* __restrict__ out, int mode)
{
    __shared__ __align__(16) uint8_t sA[64 * PPITCH];
    __shared__ __align__(16) uint8_t sW[64 * PPITCH];

    const int tid  = threadIdx.x;
    const int wid  = tid >> 5;
    const int lane = tid & 31;
    const int z = blockIdx.z;
    const int m0 = blockIdx.x * 64;
    const int n0 = blockIdx.y * 64;
    const int wm = wid >> 1;          // 0,1 : 32-row half
    const int wn = wid & 1;           // 0,1 : 32-col half

    const float* Af = (z == 0) ? q_in : (z == 1) ? k_in : v_in;
    const uint8_t* Wsp = g_wsp + (size_t)((mode == 0) ? z : 3) * 262144;
    const float* bias = (mode == 0) ? (ipb + z * E_DIM) : opb;
    const float scale = (mode == 0 && z == 0) ? SCALING : 1.0f;

    float acc[2][4][4];
#pragma unroll
    for (int a = 0; a < 2; a++)
#pragma unroll
        for (int t = 0; t < 4; t++)
#pragma unroll
            for (int j = 0; j < 4; j++) acc[a][t][j] = 0.f;

    const uint32_t sAb = smem_u32(sA), sWb = smem_u32(sW);

    for (int kc = 0; kc < 8; kc++) {
        const int koff = kc * 64;
        __syncthreads();
        // ---- stage A (64 rows) ----
        if (mode == 0) {
#pragma unroll
            for (int j = 0; j < 4; j++) {
                int i = tid + j * 128;           // 0..511
                int row = i >> 3, seg = i & 7;
                float4 v = *(const float4*)(Af + (size_t)(m0 + row) * E_DIM
                                            + kc * 32 + seg * 4);
                uint32_t h0,l0,h1,l1,h2,l2,h3,l3;
                split1(v.x,h0,l0); split1(v.y,h1,l1);
                split1(v.z,h2,l2); split1(v.w,h3,l3);
                *(uint2*)(sA + row * PPITCH + seg * 8) =
                    make_uint2(h0 | (h1<<16), h2 | (h3<<16));
                *(uint2*)(sA + row * PPITCH + 64 + seg * 8) =
                    make_uint2(l0 | (l1<<16), l2 | (l3<<16));
            }
        } else {
#pragma unroll
            for (int j = 0; j < 4; j++) {
                int i = tid + j * 128;
                int row = i >> 3, seg = i & 7;
                const uint8_t* src = g_ao + (size_t)(m0 + row) * 1024
                                   + (seg < 4 ? koff + seg * 16 : 512 + koff + (seg - 4) * 16);
                uint8_t* dst = sA + row * PPITCH + (seg < 4 ? seg * 16 : 64 + (seg - 4) * 16);
                *(uint4*)dst = *(const uint4*)src;
            }
        }
        // ---- stage W (64 rows, pre-split, raw 16B copy) ----
#pragma unroll
        for (int j = 0; j < 4; j++) {
            int i = tid + j * 128;               // 0..511
            int row = i >> 3, seg = i & 7;
            const uint8_t* src = Wsp + (size_t)(n0 + row) * 1024
                               + (seg < 4 ? koff + seg * 16 : 512 + koff + (seg - 4) * 16);
            uint8_t* dst = sW + row * PPITCH + (seg < 4 ? seg * 16 : 64 + (seg - 4) * 16);
            *(uint4*)dst = *(const uint4*)src;
        }
        __syncthreads();

#pragma unroll
        for (int ks = 0; ks < 2; ks++) {
            uint32_t ah[2][4], al[2][4];
#pragma unroll
            for (int am = 0; am < 2; am++) {
                uint32_t aaddr = sAb + (wm*32 + am*16 + (lane & 15)) * PPITCH
                               + ks*32 + (lane >> 4) * 16;
                LDSM4(ah[am], aaddr);
                LDSM4(al[am], aaddr + 64);
            }
            uint32_t bh[2][4], bl[2][4];
#pragma unroll
            for (int g = 0; g < 2; g++) {
                uint32_t baddr = sWb + (wn*32 + g*16 + (lane & 7) + ((lane >> 4) << 3)) * PPITCH
                               + ks*32 + ((lane >> 3) & 1) * 16;
                LDSM4(bh[g], baddr);
                LDSM4(bl[g], baddr + 64);
            }
            // per-accumulator grouped order (R13 proven): ah*bh, ah*bl, al*bh
#pragma unroll
            for (int am = 0; am < 2; am++)
#pragma unroll
                for (int g = 0; g < 2; g++) {
                    mma16816(acc[am][2*g+0], ah[am], bh[g][0], bh[g][1]);
                    mma16816(acc[am][2*g+0], ah[am], bl[g][0], bl[g][1]);
                    mma16816(acc[am][2*g+0], al[am], bh[g][0], bh[g][1]);
                    mma16816(acc[am][2*g+1], ah[am], bh[g][2], bh[g][3]);
                    mma16816(acc[am][2*g+1], ah[am], bl[g][2], bl[g][3]);
                    mma16816(acc[am][2*g+1], al[am], bh[g][2], bh[g][3]);
                }
        }
    }

    const int qrow = lane >> 2, qcol = (lane & 3) << 1;
    uint8_t* dstz = (z == 0) ? g_qb : (z == 1) ? g_kb : g_vb;
#pragma unroll
    for (int am = 0; am < 2; am++) {
        const int r0 = m0 + wm*32 + am*16 + qrow;
#pragma unroll
        for (int t = 0; t < 4; t++) {
            const int e = n0 + wn*32 + (t >> 1)*16 + (t & 1)*8 + qcol;
            const float b0 = bias[e], b1 = bias[e+1];
            float v00 = (acc[am][t][0] + b0) * scale;
            float v01 = (acc[am][t][1] + b1) * scale;
            float v10 = (acc[am][t][2] + b0) * scale;
            float v11 = (acc[am][t][3] + b1) * scale;
            if (mode == 0) {
                const int hh = e >> 5, d = e & 31;
#pragma unroll
                for (int half = 0; half < 2; half++) {
                    const int r = r0 + half * 8;
                    const float va = half ? v10 : v00;
                    const float vb = half ? v11 : v01;
                    const int l = r >> 2, nn = r & 3;
                    uint8_t* rp = dstz + ((size_t)(nn * H_N + hh) * L_DIM + l) * 128;
                    uint32_t ha,la,hb,lb;
                    if (z == 2) { split1h(va, ha, la); split1h(vb, hb, lb); }
                    else        { split1(va, ha, la);  split1(vb, hb, lb); }
                    *(uint32_t*)(rp + 2*d)      = ha | (hb << 16);
                    *(uint32_t*)(rp + 64 + 2*d) = la | (lb << 16);
                }
            } else {
                *(float2*)(out + (size_t)r0 * E_DIM + e)       = make_float2(v00, v01);
                *(float2*)(out + (size_t)(r0+8) * E_DIM + e)   = make_float2(v10, v11);
            }
        }
    }
}

// ---------------- Attention: HMMA flash v4 (R13 exact — 163 us) ----------------
#define KV_PITCH  144
#define REL_PITCH 36
#define SM_K(b)   ((b) * 4608)
#define SM_V(b)   (9216 + (b) * 4608)
#define SM_REL(b) (18432 + (b) * 18432)
#define SMEM_ATTN 55296

__global__ void __launch_bounds__(128, 4) attn_mma_kernel(const float* __restrict__ rel)
{
    extern __shared__ __align__(16) uint8_t smem[];
    const int tid  = threadIdx.x;
    const int wid  = tid >> 5;
    const int lane = tid & 31;
    const int bh = blockIdx.y;
    const int l0 = blockIdx.x * 128;
    const int WROW = wid * 32;

    const uint32_t sb = smem_u32(smem);
    const uint4* ksrc = (const uint4*)(g_kb + (size_t)bh * S_DIM * 128);
    const uint4* vsrc = (const uint4*)(g_vb + (size_t)bh * S_DIM * 128);
    const float* relg = rel + ((size_t)bh * L_DIM + l0) * S_DIM;

    {
        const uint4* qs = (const uint4*)(g_qb + ((size_t)bh * L_DIM + l0) * 128);
        uint32_t qb = sb + SM_REL(0);
#pragma unroll
        for (int j = 0; j < 8; j++) {
            int i = tid + j * 128;
            CP16(qb + (i >> 3) * KV_PITCH + (i & 7) * 16, qs + i);
        }
        CP_COMMIT(); CP_WAIT0();
    }
    __syncthreads();
    uint32_t qh0[2][4], qh1[2][4], ql0[2][4], ql1[2][4];
#pragma unroll
    for (int am = 0; am < 2; am++) {
        uint32_t qaddr = sb + SM_REL(0) + (WROW + 16*am + (lane & 15)) * KV_PITCH
                       + (lane >> 4) * 16;
        LDSM4(qh0[am], qaddr);
        LDSM4(qh1[am], qaddr + 32);
        LDSM4(ql0[am], qaddr + 64);
        LDSM4(ql1[am], qaddr + 96);
    }
    __syncthreads();

    {
#pragma unroll
        for (int j = 0; j < 2; j++) {
            int i = tid + j * 128;
            uint32_t o = (i >> 3) * KV_PITCH + (i & 7) * 16;
            CP16(sb + SM_K(0) + o, ksrc + i);
            CP16(sb + SM_V(0) + o, vsrc + i);
        }
#pragma unroll
        for (int j = 0; j < 8; j++) {
            int i = tid + j * 128;
            int row = i >> 3, seg = i & 7;
            CP16(sb + SM_REL(0) + row * (REL_PITCH * 4) + seg * 16,
                 (const uint4*)(relg + (size_t)row * S_DIM) + seg);
        }
        CP_COMMIT();
    }

    float O[2][4][4];
#pragma unroll
    for (int am = 0; am < 2; am++)
#pragma unroll
        for (int t = 0; t < 4; t++)
#pragma unroll
            for (int j = 0; j < 4; j++) O[am][t][j] = 0.f;
    float rs[2][2] = {{0.f, 0.f}, {0.f, 0.f}};

    const int qrow = lane >> 2;
    const int qcol = (lane & 3) << 1;

    for (int c = 0; c < S_DIM / 32; ++c) {
        const int cur = c & 1;
        if (c + 1 < S_DIM / 32) {
            const int nxt = cur ^ 1;
            const int s1 = (c + 1) * 32;
#pragma unroll
            for (int j = 0; j < 2; j++) {
                int i = tid + j * 128;
                uint32_t o = (i >> 3) * KV_PITCH + (i & 7) * 16;
                CP16(sb + SM_K(nxt) + o, ksrc + (c + 1) * 256 + i);
                CP16(sb + SM_V(nxt) + o, vsrc + (c + 1) * 256 + i);
            }
#pragma unroll
            for (int j = 0; j < 8; j++) {
                int i = tid + j * 128;
                int row = i >> 3, seg = i & 7;
                CP16(sb + SM_REL(nxt) + row * (REL_PITCH * 4) + seg * 16,
                     (const uint4*)(relg + (size_t)row * S_DIM + s1) + seg);
            }
            CP_COMMIT();
            CP_WAIT1();
        } else {
            CP_WAIT0();
        }
        __syncthreads();

        const float* srel = (const float*)(smem + SM_REL(cur));
        const uint32_t skb = sb + SM_K(cur), svb = sb + SM_V(cur);

#pragma unroll
        for (int np = 0; np < 2; np++) {
            uint32_t kaddr = skb + (16*np + (lane & 7) + ((lane >> 4) << 3)) * KV_PITCH
                           + ((lane >> 3) & 1) * 16;
            uint32_t kh0[4], kh1[4], kl0[4], kl1[4];
            LDSM4(kh0, kaddr);
            LDSM4(kh1, kaddr + 32);
            LDSM4(kl0, kaddr + 64);
            LDSM4(kl1, kaddr + 96);
            uint32_t vaddr = svb + (16*np + (lane & 15)) * KV_PITCH + (lane >> 4) * 16;
            uint32_t vh0[4], vh1[4], vl0[4], vl1[4];
            LDSM4T(vh0, vaddr);
            LDSM4T(vh1, vaddr + 32);
            LDSM4T(vl0, vaddr + 64);
            LDSM4T(vl1, vaddr + 96);

#pragma unroll
            for (int am = 0; am < 2; am++) {
                const float* r0 = srel + (WROW + 16*am + qrow) * REL_PITCH + 16*np + qcol;
                float cA[4], cB[4];
                {
                    float2 t0 = *(const float2*)(r0);
                    float2 t1 = *(const float2*)(r0 + 8 * REL_PITCH);
                    float2 t2 = *(const float2*)(r0 + 8);
                    float2 t3 = *(const float2*)(r0 + 8 * REL_PITCH + 8);
                    cA[0]=t0.x; cA[1]=t0.y; cA[2]=t1.x; cA[3]=t1.y;
                    cB[0]=t2.x; cB[1]=t2.y; cB[2]=t3.x; cB[3]=t3.y;
                }
                // QK: 3-term bf16 split (R13 grouped order)
                mma16816(cA, qh0[am], kh0[0], kh0[1]);
                mma16816(cA, qh1[am], kh1[0], kh1[1]);
                mma16816(cA, qh0[am], kl0[0], kl0[1]);
                mma16816(cA, qh1[am], kl1[0], kl1[1]);
                mma16816(cA, ql0[am], kh0[0], kh0[1]);
                mma16816(cA, ql1[am], kh1[0], kh1[1]);

                mma16816(cB, qh0[am], kh0[2], kh0[3]);
                mma16816(cB, qh1[am], kh1[2], kh1[3]);
                mma16816(cB, qh0[am], kl0[2], kl0[3]);
                mma16816(cB, qh1[am], kl1[2], kl1[3]);
                mma16816(cB, ql0[am], kh0[2], kh0[3]);
                mma16816(cB, ql1[am], kh1[2], kh1[3]);

                // exp + sums + fp16 pack
                float pA0 = __expf(cA[0]), pA1 = __expf(cA[1]);
                float pA2 = __expf(cA[2]), pA3 = __expf(cA[3]);
                float pB0 = __expf(cB[0]), pB1 = __expf(cB[1]);
                float pB2 = __expf(cB[2]), pB3 = __expf(cB[3]);
                rs[am][0] += (pA0 + pA1) + (pB0 + pB1);
                rs[am][1] += (pA2 + pA3) + (pB2 + pB3);

                uint32_t phi[4];
                phi[0] = packh2(pA0, pA1); phi[1] = packh2(pA2, pA3);
                phi[2] = packh2(pB0, pB1); phi[3] = packh2(pB2, pB3);

                // AV: fp16 P x (Vhi + Vlo) (R13 grouped order)
                mma16816h(O[am][0], phi, vh0[0], vh0[1]);
                mma16816h(O[am][0], phi, vl0[0], vl0[1]);

                mma16816h(O[am][1], phi, vh0[2], vh0[3]);
                mma16816h(O[am][1], phi, vl0[2], vl0[3]);

                mma16816h(O[am][2], phi, vh1[0], vh1[1]);
                mma16816h(O[am][2], phi, vl1[0], vl1[1]);

                mma16816h(O[am][3], phi, vh1[2], vh1[3]);
                mma16816h(O[am][3], phi, vl1[2], vl1[3]);
            }
        }
        __syncthreads();
    }

    // ---- epilogue ----
    const int n = bh >> 3, h = bh & 7;
#pragma unroll
    for (int am = 0; am < 2; am++) {
        float s0 = rs[am][0], s1 = rs[am][1];
        s0 += __shfl_xor_sync(0xffffffffu, s0, 1);
        s0 += __shfl_xor_sync(0xffffffffu, s0, 2);
        s1 += __shfl_xor_sync(0xffffffffu, s1, 1);
        s1 += __shfl_xor_sync(0xffffffffu, s1, 2);
        const float inv0 = 1.0f / s0, inv1 = 1.0f / s1;

        const int r = l0 + WROW + 16*am + qrow;
        uint8_t* rp0 = g_ao + ((size_t)r * N_B + n) * 1024;
        uint8_t* rp8 = rp0 + (size_t)8 * N_B * 1024;
#pragma unroll
        for (int t = 0; t < 4; t++) {
            const int e = h * HD_N + t * 8 + qcol;
            uint32_t ha, la, hb, lb;
            split1(O[am][t][0] * inv0, ha, la); split1(O[am][t][1] * inv0, hb, lb);
            *(uint32_t*)(rp0 + 2*e)       = ha | (hb << 16);
            *(uint32_t*)(rp0 + 512 + 2*e) = la | (lb << 16);
            split1(O[am][t][2] * inv1, ha, la); split1(O[am][t][3] * inv1, hb, lb);
            *(uint32_t*)(rp8 + 2*e)       = ha | (hb << 16);
            *(uint32_t*)(rp8 + 512 + 2*e) = la | (lb << 16);
        }
    }
}

// ---------------------------------------------------------------------------
extern "C" void kernel_launch(void* const* d_in, const int* in_sizes, int n_in,
                              void* d_out, int out_size)
{
    const float* query = (const float*)d_in[0];
    const float* key   = (const float*)d_in[1];
    const float* value = (const float*)d_in[2];
    const float* rel   = (const float*)d_in[3];
    const float* ipw   = (const float*)d_in[4];
    const float* ipb   = (const float*)d_in[5];
    const float* opw   = (const float*)d_in[6];
    const float* opb   = (const float*)d_in[7];
    float* out = (float*)d_out;

    cudaFuncSetAttribute(attn_mma_kernel,
                         cudaFuncAttributeMaxDynamicSharedMemorySize, SMEM_ATTN);

    convert_w_kernel<<<dim3(64, 4), 256>>>(ipw, opw);

    proj_mma_kernel<<<dim3(128, 4, 3), 128>>>(query, key, value, ipb, opb, out, 0);

    attn_mma_kernel<<<dim3(16, 32), 128, SMEM_ATTN>>>(rel);

    proj_mma_kernel<<<dim3(128, 4, 1), 128>>>(query, key, value, ipb, opb, out, 1);
}

// round 16
// speedup vs baseline: 1.0436x; 1.0247x over previous
#include <cuda_runtime.h>
#include <cuda_bf16.h>
#include <cuda_fp16.h>
#include <math.h>
#include <stdint.h>

#define L_DIM 2048
#define S_DIM 2048
#define N_B   4
#define E_DIM 256
#define H_N   8
#define HD_N  32
#define NH_N  32
#define SCALING 0.17677669529663687f

__device__ __align__(128) uint8_t g_qb[(size_t)NH_N * L_DIM * 128];
__device__ __align__(128) uint8_t g_kb[(size_t)NH_N * S_DIM * 128];
__device__ __align__(128) uint8_t g_vb[(size_t)NH_N * S_DIM * 128];
__device__ __align__(128) uint8_t g_wsp[(size_t)4 * 256 * 1024];
__device__ __align__(128) uint8_t g_ao[(size_t)8192 * 1024];

// ---------------- helpers ----------------
__device__ __forceinline__ uint32_t smem_u32(const void* p) {
    uint32_t a;
    asm("{ .reg .u64 t; cvta.to.shared.u64 t, %1; cvt.u32.u64 %0, t; }" : "=r"(a) : "l"(p));
    return a;
}
__device__ __forceinline__ uint32_t packh2(float a, float b) {
    __half2 t = __floats2half2_rn(a, b);
    return *(uint32_t*)&t;
}
__device__ __forceinline__ void split1(float v, uint32_t& hi16, uint32_t& lo16) {
    __nv_bfloat16 h = __float2bfloat16(v);
    __nv_bfloat16 l = __float2bfloat16(v - __bfloat162float(h));
    hi16 = __bfloat16_as_ushort(h);
    lo16 = __bfloat16_as_ushort(l);
}
__device__ __forceinline__ void split1h(float v, uint32_t& hi16, uint32_t& lo16) {
    __half h = __float2half_rn(v);
    __half l = __float2half_rn(v - __half2float(h));
    hi16 = __half_as_ushort(h);
    lo16 = __half_as_ushort(l);
}

#define LDSM4(R, addr)                                                          \
    asm volatile("ldmatrix.sync.aligned.m8n8.x4.shared.b16 {%0,%1,%2,%3}, [%4];" \
        : "=r"((R)[0]), "=r"((R)[1]), "=r"((R)[2]), "=r"((R)[3]) : "r"(addr))
#define LDSM4T(R, addr)                                                         \
    asm volatile("ldmatrix.sync.aligned.m8n8.x4.trans.shared.b16 {%0,%1,%2,%3}, [%4];" \
        : "=r"((R)[0]), "=r"((R)[1]), "=r"((R)[2]), "=r"((R)[3]) : "r"(addr))
#define CP16(dst, src)                                                          \
    asm volatile("cp.async.cg.shared.global [%0], [%1], 16;" :: "r"(dst), "l"(src))
#define CP_COMMIT() asm volatile("cp.async.commit_group;")
#define CP_WAIT0()  asm volatile("cp.async.wait_group 0;")
#define CP_WAIT1()  asm volatile("cp.async.wait_group 1;")

__device__ __forceinline__ void mma16816(float c[4], const uint32_t a[4],
                                         uint32_t b0, uint32_t b1) {
    asm volatile("mma.sync.aligned.m16n8k16.row.col.f32.bf16.bf16.f32 "
        "{%0,%1,%2,%3}, {%4,%5,%6,%7}, {%8,%9}, {%0,%1,%2,%3};"
        : "+f"(c[0]), "+f"(c[1]), "+f"(c[2]), "+f"(c[3])
        : "r"(a[0]), "r"(a[1]), "r"(a[2]), "r"(a[3]), "r"(b0), "r"(b1));
}
__device__ __forceinline__ void mma16816h(float c[4], const uint32_t a[4],
                                          uint32_t b0, uint32_t b1) {
    asm volatile("mma.sync.aligned.m16n8k16.row.col.f32.f16.f16.f32 "
        "{%0,%1,%2,%3}, {%4,%5,%6,%7}, {%8,%9}, {%0,%1,%2,%3};"
        : "+f"(c[0]), "+f"(c[1]), "+f"(c[2]), "+f"(c[3])
        : "r"(a[0]), "r"(a[1]), "r"(a[2]), "r"(a[3]), "r"(b0), "r"(b1));
}

// ---------------- weight conversion (once; tiny) ----------------
__global__ __launch_bounds__(256)
void convert_w_kernel(const float* __restrict__ ipw, const float* __restrict__ opw)
{
    const int z = blockIdx.y;
    const float* src = (z < 3) ? (ipw + (size_t)z * 65536) : opw;
    uint8_t* dst = g_wsp + (size_t)z * 262144;
    size_t g = ((size_t)blockIdx.x * 256 + threadIdx.x) * 4;
    float4 v = *(const float4*)(src + g);
    uint32_t h0,l0,h1,l1,h2,l2,h3,l3;
    split1(v.x,h0,l0); split1(v.y,h1,l1); split1(v.z,h2,l2); split1(v.w,h3,l3);
    size_t row = g >> 8;
    int c = (int)(g & 255);
    uint8_t* rp = dst + row * 1024;
    *(uint2*)(rp + 2*c)       = make_uint2(h0 | (h1<<16), h2 | (h3<<16));
    *(uint2*)(rp + 512 + 2*c) = make_uint2(l0 | (l1<<16), l2 | (l3<<16));
}

// ---------------- HMMA projection GEMM, 64m x 128n (R13 geometry) ----------------
// cp.async pipelined: W double-buffered; mode-1 A async; mode-0 A sync split.
// Dynamic smem: sA (64*144) + sW[2] (2 * 128*144) = 46080 B.
#define PPITCH 144
#define PSM_A    0
#define PSM_W(b) (9216 + (b) * 18432)
#define SMEM_PROJ 46080

__global__ __launch_bounds__(128)
void proj_mma_kernel(const float* __restrict__ q_in, const float* __restrict__ k_in,
                     const float* __restrict__ v_in,
                     const float* __restrict__ ipb, const float* __restrict__ opb,
                     float* __restrict__ out, int mode)
{
    extern __shared__ __align__(16) uint8_t psm[];
    uint8_t* sA = psm;

    const int tid  = threadIdx.x;
    const int wid  = tid >> 5;
    const int lane = tid & 31;
    const int z = blockIdx.z;
    const int m0 = blockIdx.x * 64;
    const int n0 = blockIdx.y * 128;
    const int wm = wid >> 1;
    const int wn = wid & 1;

    const float* Af = (z == 0) ? q_in : (z == 1) ? k_in : v_in;
    const uint8_t* Wsp = g_wsp + (size_t)((mode == 0) ? z : 3) * 262144;
    const float* bias = (mode == 0) ? (ipb + z * E_DIM) : opb;
    const float scale = (mode == 0 && z == 0) ? SCALING : 1.0f;

    const uint32_t sb = smem_u32(psm);

    float acc[2][8][4];
#pragma unroll
    for (int a = 0; a < 2; a++)
#pragma unroll
        for (int t = 0; t < 8; t++)
#pragma unroll
            for (int j = 0; j < 4; j++) acc[a][t][j] = 0.f;

    // ---- prologue: async-stage W(kc=0) into buf 0 ----
    {
#pragma unroll
        for (int j = 0; j < 8; j++) {
            int i = tid + j * 128;
            int row = i >> 3, seg = i & 7;
            const uint8_t* src = Wsp + (size_t)(n0 + row) * 1024
                               + (seg < 4 ? seg * 16 : 512 + (seg - 4) * 16);
            CP16(sb + PSM_W(0) + row * PPITCH + (seg < 4 ? seg * 16 : 64 + (seg - 4) * 16),
                 src);
        }
        CP_COMMIT();
    }

    for (int kc = 0; kc < 8; kc++) {
        const int wb = kc & 1;
        const int koff = kc * 64;
        __syncthreads();   // prior compute done with sA / sW[wb]
        // ---- stage A(kc) ----
        if (mode == 0) {
#pragma unroll
            for (int j = 0; j < 4; j++) {
                int i = tid + j * 128;
                int row = i >> 3, seg = i & 7;
                float4 v = *(const float4*)(Af + (size_t)(m0 + row) * E_DIM
                                            + kc * 32 + seg * 4);
                uint32_t h0,l0,h1,l1,h2,l2,h3,l3;
                split1(v.x,h0,l0); split1(v.y,h1,l1);
                split1(v.z,h2,l2); split1(v.w,h3,l3);
                *(uint2*)(sA + row * PPITCH + seg * 8) =
                    make_uint2(h0 | (h1<<16), h2 | (h3<<16));
                *(uint2*)(sA + row * PPITCH + 64 + seg * 8) =
                    make_uint2(l0 | (l1<<16), l2 | (l3<<16));
            }
        } else {
#pragma unroll
            for (int j = 0; j < 4; j++) {
                int i = tid + j * 128;
                int row = i >> 3, seg = i & 7;
                const uint8_t* src = g_ao + (size_t)(m0 + row) * 1024
                                   + (seg < 4 ? koff + seg * 16 : 512 + koff + (seg - 4) * 16);
                CP16(sb + PSM_A + row * PPITCH + (seg < 4 ? seg * 16 : 64 + (seg - 4) * 16),
                     src);
            }
            CP_COMMIT();   // group: A(kc)
        }
        // ---- async-stage W(kc+1) into the other buffer ----
        if (kc + 1 < 8) {
            const int koff1 = (kc + 1) * 64;
#pragma unroll
            for (int j = 0; j < 8; j++) {
                int i = tid + j * 128;
                int row = i >> 3, seg = i & 7;
                const uint8_t* src = Wsp + (size_t)(n0 + row) * 1024
                                   + (seg < 4 ? koff1 + seg * 16 : 512 + koff1 + (seg - 4) * 16);
                CP16(sb + PSM_W(wb ^ 1) + row * PPITCH
                         + (seg < 4 ? seg * 16 : 64 + (seg - 4) * 16),
                     src);
            }
            CP_COMMIT();   // group: W(kc+1)
            CP_WAIT1();    // A(kc) [mode1] + W(kc) complete; W(kc+1) in flight
        } else {
            CP_WAIT0();
        }
        __syncthreads();

        const uint32_t sWb = sb + PSM_W(wb);
#pragma unroll
        for (int ks = 0; ks < 2; ks++) {
            uint32_t ah[2][4], al[2][4];
#pragma unroll
            for (int am = 0; am < 2; am++) {
                uint32_t aaddr = sb + PSM_A + (wm*32 + am*16 + (lane & 15)) * PPITCH
                               + ks*32 + (lane >> 4) * 16;
                LDSM4(ah[am], aaddr);
                LDSM4(al[am], aaddr + 64);
            }
            uint32_t bh[4][4], bl[4][4];
#pragma unroll
            for (int g = 0; g < 4; g++) {
                uint32_t baddr = sWb + (wn*64 + g*16 + (lane & 7) + ((lane >> 4) << 3)) * PPITCH
                               + ks*32 + ((lane >> 3) & 1) * 16;
                LDSM4(bh[g], baddr);
                LDSM4(bl[g], baddr + 64);
            }
#pragma unroll
            for (int am = 0; am < 2; am++)
#pragma unroll
                for (int g = 0; g < 4; g++) {
                    mma16816(acc[am][2*g+0], ah[am], bh[g][0], bh[g][1]);
                    mma16816(acc[am][2*g+0], ah[am], bl[g][0], bl[g][1]);
                    mma16816(acc[am][2*g+0], al[am], bh[g][0], bh[g][1]);
                    mma16816(acc[am][2*g+1], ah[am], bh[g][2], bh[g][3]);
                    mma16816(acc[am][2*g+1], ah[am], bl[g][2], bl[g][3]);
                    mma16816(acc[am][2*g+1], al[am], bh[g][2], bh[g][3]);
                }
        }
    }

    const int qrow = lane >> 2, qcol = (lane & 3) << 1;
    uint8_t* dstz = (z == 0) ? g_qb : (z == 1) ? g_kb : g_vb;
#pragma unroll
    for (int am = 0; am < 2; am++) {
        const int r0 = m0 + wm*32 + am*16 + qrow;
#pragma unroll
        for (int t = 0; t < 8; t++) {
            const int e = n0 + wn*64 + (t >> 1)*16 + (t & 1)*8 + qcol;
            const float b0 = bias[e], b1 = bias[e+1];
            float v00 = (acc[am][t][0] + b0) * scale;
            float v01 = (acc[am][t][1] + b1) * scale;
            float v10 = (acc[am][t][2] + b0) * scale;
            float v11 = (acc[am][t][3] + b1) * scale;
            if (mode == 0) {
                const int hh = e >> 5, d = e & 31;
#pragma unroll
                for (int half = 0; half < 2; half++) {
                    const int r = r0 + half * 8;
                    const float va = half ? v10 : v00;
                    const float vb = half ? v11 : v01;
                    const int l = r >> 2, nn = r & 3;
                    uint8_t* rp = dstz + ((size_t)(nn * H_N + hh) * L_DIM + l) * 128;
                    uint32_t ha,la,hb,lb;
                    if (z == 2) { split1h(va, ha, la); split1h(vb, hb, lb); }
                    else        { split1(va, ha, la);  split1(vb, hb, lb); }
                    *(uint32_t*)(rp + 2*d)      = ha | (hb << 16);
                    *(uint32_t*)(rp + 64 + 2*d) = la | (lb << 16);
                }
            } else {
                *(float2*)(out + (size_t)r0 * E_DIM + e)       = make_float2(v00, v01);
                *(float2*)(out + (size_t)(r0+8) * E_DIM + e)   = make_float2(v10, v11);
            }
        }
    }
}

// ---------------- Attention: HMMA flash v4 (R13 exact — 163 us) ----------------
#define KV_PITCH  144
#define REL_PITCH 36
#define SM_K(b)   ((b) * 4608)
#define SM_V(b)   (9216 + (b) * 4608)
#define SM_REL(b) (18432 + (b) * 18432)
#define SMEM_ATTN 55296

__global__ void __launch_bounds__(128, 4) attn_mma_kernel(const float* __restrict__ rel)
{
    extern __shared__ __align__(16) uint8_t smem[];
    const int tid  = threadIdx.x;
    const int wid  = tid >> 5;
    const int lane = tid & 31;
    const int bh = blockIdx.y;
    const int l0 = blockIdx.x * 128;
    const int WROW = wid * 32;

    const uint32_t sb = smem_u32(smem);
    const uint4* ksrc = (const uint4*)(g_kb + (size_t)bh * S_DIM * 128);
    const uint4* vsrc = (const uint4*)(g_vb + (size_t)bh * S_DIM * 128);
    const float* relg = rel + ((size_t)bh * L_DIM + l0) * S_DIM;

    {
        const uint4* qs = (const uint4*)(g_qb + ((size_t)bh * L_DIM + l0) * 128);
        uint32_t qb = sb + SM_REL(0);
#pragma unroll
        for (int j = 0; j < 8; j++) {
            int i = tid + j * 128;
            CP16(qb + (i >> 3) * KV_PITCH + (i & 7) * 16, qs + i);
        }
        CP_COMMIT(); CP_WAIT0();
    }
    __syncthreads();
    uint32_t qh0[2][4], qh1[2][4], ql0[2][4], ql1[2][4];
#pragma unroll
    for (int am = 0; am < 2; am++) {
        uint32_t qaddr = sb + SM_REL(0) + (WROW + 16*am + (lane & 15)) * KV_PITCH
                       + (lane >> 4) * 16;
        LDSM4(qh0[am], qaddr);
        LDSM4(qh1[am], qaddr + 32);
        LDSM4(ql0[am], qaddr + 64);
        LDSM4(ql1[am], qaddr + 96);
    }
    __syncthreads();

    {
#pragma unroll
        for (int j = 0; j < 2; j++) {
            int i = tid + j * 128;
            uint32_t o = (i >> 3) * KV_PITCH + (i & 7) * 16;
            CP16(sb + SM_K(0) + o, ksrc + i);
            CP16(sb + SM_V(0) + o, vsrc + i);
        }
#pragma unroll
        for (int j = 0; j < 8; j++) {
            int i = tid + j * 128;
            int row = i >> 3, seg = i & 7;
            CP16(sb + SM_REL(0) + row * (REL_PITCH * 4) + seg * 16,
                 (const uint4*)(relg + (size_t)row * S_DIM) + seg);
        }
        CP_COMMIT();
    }

    float O[2][4][4];
#pragma unroll
    for (int am = 0; am < 2; am++)
#pragma unroll
        for (int t = 0; t < 4; t++)
#pragma unroll
            for (int j = 0; j < 4; j++) O[am][t][j] = 0.f;
    float rs[2][2] = {{0.f, 0.f}, {0.f, 0.f}};

    const int qrow = lane >> 2;
    const int qcol = (lane & 3) << 1;

    for (int c = 0; c < S_DIM / 32; ++c) {
        const int cur = c & 1;
        if (c + 1 < S_DIM / 32) {
            const int nxt = cur ^ 1;
            const int s1 = (c + 1) * 32;
#pragma unroll
            for (int j = 0; j < 2; j++) {
                int i = tid + j * 128;
                uint32_t o = (i >> 3) * KV_PITCH + (i & 7) * 16;
                CP16(sb + SM_K(nxt) + o, ksrc + (c + 1) * 256 + i);
                CP16(sb + SM_V(nxt) + o, vsrc + (c + 1) * 256 + i);
            }
#pragma unroll
            for (int j = 0; j < 8; j++) {
                int i = tid + j * 128;
                int row = i >> 3, seg = i & 7;
                CP16(sb + SM_REL(nxt) + row * (REL_PITCH * 4) + seg * 16,
                     (const uint4*)(relg + (size_t)row * S_DIM + s1) + seg);
            }
            CP_COMMIT();
            CP_WAIT1();
        } else {
            CP_WAIT0();
        }
        __syncthreads();

        const float* srel = (const float*)(smem + SM_REL(cur));
        const uint32_t skb = sb + SM_K(cur), svb = sb + SM_V(cur);

#pragma unroll
        for (int np = 0; np < 2; np++) {
            uint32_t kaddr = skb + (16*np + (lane & 7) + ((lane >> 4) << 3)) * KV_PITCH
                           + ((lane >> 3) & 1) * 16;
            uint32_t kh0[4], kh1[4], kl0[4], kl1[4];
            LDSM4(kh0, kaddr);
            LDSM4(kh1, kaddr + 32);
            LDSM4(kl0, kaddr + 64);
            LDSM4(kl1, kaddr + 96);
            uint32_t vaddr = svb + (16*np + (lane & 15)) * KV_PITCH + (lane >> 4) * 16;
            uint32_t vh0[4], vh1[4], vl0[4], vl1[4];
            LDSM4T(vh0, vaddr);
            LDSM4T(vh1, vaddr + 32);
            LDSM4T(vl0, vaddr + 64);
            LDSM4T(vl1, vaddr + 96);

#pragma unroll
            for (int am = 0; am < 2; am++) {
                const float* r0 = srel + (WROW + 16*am + qrow) * REL_PITCH + 16*np + qcol;
                float cA[4], cB[4];
                {
                    float2 t0 = *(const float2*)(r0);
                    float2 t1 = *(const float2*)(r0 + 8 * REL_PITCH);
                    float2 t2 = *(const float2*)(r0 + 8);
                    float2 t3 = *(const float2*)(r0 + 8 * REL_PITCH + 8);
                    cA[0]=t0.x; cA[1]=t0.y; cA[2]=t1.x; cA[3]=t1.y;
                    cB[0]=t2.x; cB[1]=t2.y; cB[2]=t3.x; cB[3]=t3.y;
                }
                mma16816(cA, qh0[am], kh0[0], kh0[1]);
                mma16816(cA, qh1[am], kh1[0], kh1[1]);
                mma16816(cA, qh0[am], kl0[0], kl0[1]);
                mma16816(cA, qh1[am], kl1[0], kl1[1]);
                mma16816(cA, ql0[am], kh0[0], kh0[1]);
                mma16816(cA, ql1[am], kh1[0], kh1[1]);

                mma16816(cB, qh0[am], kh0[2], kh0[3]);
                mma16816(cB, qh1[am], kh1[2], kh1[3]);
                mma16816(cB, qh0[am], kl0[2], kl0[3]);
                mma16816(cB, qh1[am], kl1[2], kl1[3]);
                mma16816(cB, ql0[am], kh0[2], kh0[3]);
                mma16816(cB, ql1[am], kh1[2], kh1[3]);

                float pA0 = __expf(cA[0]), pA1 = __expf(cA[1]);
                float pA2 = __expf(cA[2]), pA3 = __expf(cA[3]);
                float pB0 = __expf(cB[0]), pB1 = __expf(cB[1]);
                float pB2 = __expf(cB[2]), pB3 = __expf(cB[3]);
                rs[am][0] += (pA0 + pA1) + (pB0 + pB1);
                rs[am][1] += (pA2 + pA3) + (pB2 + pB3);

                uint32_t phi[4];
                phi[0] = packh2(pA0, pA1); phi[1] = packh2(pA2, pA3);
                phi[2] = packh2(pB0, pB1); phi[3] = packh2(pB2, pB3);

                mma16816h(O[am][0], phi, vh0[0], vh0[1]);
                mma16816h(O[am][0], phi, vl0[0], vl0[1]);

                mma16816h(O[am][1], phi, vh0[2], vh0[3]);
                mma16816h(O[am][1], phi, vl0[2], vl0[3]);

                mma16816h(O[am][2], phi, vh1[0], vh1[1]);
                mma16816h(O[am][2], phi, vl1[0], vl1[1]);

                mma16816h(O[am][3], phi, vh1[2], vh1[3]);
                mma16816h(O[am][3], phi, vl1[2], vl1[3]);
            }
        }
        __syncthreads();
    }

    // ---- epilogue ----
    const int n = bh >> 3, h = bh & 7;
#pragma unroll
    for (int am = 0; am < 2; am++) {
        float s0 = rs[am][0], s1 = rs[am][1];
        s0 += __shfl_xor_sync(0xffffffffu, s0, 1);
        s0 += __shfl_xor_sync(0xffffffffu, s0, 2);
        s1 += __shfl_xor_sync(0xffffffffu, s1, 1);
        s1 += __shfl_xor_sync(0xffffffffu, s1, 2);
        const float inv0 = 1.0f / s0, inv1 = 1.0f / s1;

        const int r = l0 + WROW + 16*am + qrow;
        uint8_t* rp0 = g_ao + ((size_t)r * N_B + n) * 1024;
        uint8_t* rp8 = rp0 + (size_t)8 * N_B * 1024;
#pragma unroll
        for (int t = 0; t < 4; t++) {
            const int e = h * HD_N + t * 8 + qcol;
            uint32_t ha, la, hb, lb;
            split1(O[am][t][0] * inv0, ha, la); split1(O[am][t][1] * inv0, hb, lb);
            *(uint32_t*)(rp0 + 2*e)       = ha | (hb << 16);
            *(uint32_t*)(rp0 + 512 + 2*e) = la | (lb << 16);
            split1(O[am][t][2] * inv1, ha, la); split1(O[am][t][3] * inv1, hb, lb);
            *(uint32_t*)(rp8 + 2*e)       = ha | (hb << 16);
            *(uint32_t*)(rp8 + 512 + 2*e) = la | (lb << 16);
        }
    }
}

// ---------------------------------------------------------------------------
extern "C" void kernel_launch(void* const* d_in, const int* in_sizes, int n_in,
                              void* d_out, int out_size)
{
    const float* query = (const float*)d_in[0];
    const float* key   = (const float*)d_in[1];
    const float* value = (const float*)d_in[2];
    const float* rel   = (const float*)d_in[3];
    const float* ipw   = (const float*)d_in[4];
    const float* ipb   = (const float*)d_in[5];
    const float* opw   = (const float*)d_in[6];
    const float* opb   = (const float*)d_in[7];
    float* out = (float*)d_out;

    cudaFuncSetAttribute(attn_mma_kernel,
                         cudaFuncAttributeMaxDynamicSharedMemorySize, SMEM_ATTN);
    cudaFuncSetAttribute(proj_mma_kernel,
                         cudaFuncAttributeMaxDynamicSharedMemorySize, SMEM_PROJ);

    convert_w_kernel<<<dim3(64, 4), 256>>>(ipw, opw);

    proj_mma_kernel<<<dim3(128, 2, 3), 128, SMEM_PROJ>>>(query, key, value,
                                                         ipb, opb, out, 0);

    attn_mma_kernel<<<dim3(16, 32), 128, SMEM_ATTN>>>(rel);

    proj_mma_kernel<<<dim3(128, 2, 1), 128, SMEM_PROJ>>>(query, key, value,
                                                         ipb, opb, out, 1);
}

// round 17
// speedup vs baseline: 1.0665x; 1.0220x over previous
#include <cuda_runtime.h>
#include <cuda_bf16.h>
#include <cuda_fp16.h>
#include <math.h>
#include <stdint.h>

#define L_DIM 2048
#define S_DIM 2048
#define N_B   4
#define E_DIM 256
#define H_N   8
#define HD_N  32
#define NH_N  32
#define SCALING 0.17677669529663687f

__device__ __align__(128) uint8_t g_qb[(size_t)NH_N * L_DIM * 128];
__device__ __align__(128) uint8_t g_kb[(size_t)NH_N * S_DIM * 128];
__device__ __align__(128) uint8_t g_vb[(size_t)NH_N * S_DIM * 128];
__device__ __align__(128) uint8_t g_wsp[(size_t)4 * 256 * 1024];   // z<3 bf16 hi|lo, z=3 fp16 hi|lo
__device__ __align__(128) uint8_t g_ao[(size_t)8192 * 512];        // fp16 single, 512B rows

// ---------------- helpers ----------------
__device__ __forceinline__ uint32_t smem_u32(const void* p) {
    uint32_t a;
    asm("{ .reg .u64 t; cvta.to.shared.u64 t, %1; cvt.u32.u64 %0, t; }" : "=r"(a) : "l"(p));
    return a;
}
__device__ __forceinline__ uint32_t packh2(float a, float b) {
    __half2 t = __floats2half2_rn(a, b);
    return *(uint32_t*)&t;
}
__device__ __forceinline__ void split1(float v, uint32_t& hi16, uint32_t& lo16) {
    __nv_bfloat16 h = __float2bfloat16(v);
    __nv_bfloat16 l = __float2bfloat16(v - __bfloat162float(h));
    hi16 = __bfloat16_as_ushort(h);
    lo16 = __bfloat16_as_ushort(l);
}
__device__ __forceinline__ void split1h(float v, uint32_t& hi16, uint32_t& lo16) {
    __half h = __float2half_rn(v);
    __half l = __float2half_rn(v - __half2float(h));
    hi16 = __half_as_ushort(h);
    lo16 = __half_as_ushort(l);
}

#define LDSM4(R, addr)                                                          \
    asm volatile("ldmatrix.sync.aligned.m8n8.x4.shared.b16 {%0,%1,%2,%3}, [%4];" \
        : "=r"((R)[0]), "=r"((R)[1]), "=r"((R)[2]), "=r"((R)[3]) : "r"(addr))
#define LDSM4T(R, addr)                                                         \
    asm volatile("ldmatrix.sync.aligned.m8n8.x4.trans.shared.b16 {%0,%1,%2,%3}, [%4];" \
        : "=r"((R)[0]), "=r"((R)[1]), "=r"((R)[2]), "=r"((R)[3]) : "r"(addr))
#define CP16(dst, src)                                                          \
    asm volatile("cp.async.cg.shared.global [%0], [%1], 16;" :: "r"(dst), "l"(src))
#define CP_COMMIT() asm volatile("cp.async.commit_group;")
#define CP_WAIT0()  asm volatile("cp.async.wait_group 0;")
#define CP_WAIT1()  asm volatile("cp.async.wait_group 1;")

__device__ __forceinline__ void mma16816(float c[4], const uint32_t a[4],
                                         uint32_t b0, uint32_t b1) {
    asm volatile("mma.sync.aligned.m16n8k16.row.col.f32.bf16.bf16.f32 "
        "{%0,%1,%2,%3}, {%4,%5,%6,%7}, {%8,%9}, {%0,%1,%2,%3};"
        : "+f"(c[0]), "+f"(c[1]), "+f"(c[2]), "+f"(c[3])
        : "r"(a[0]), "r"(a[1]), "r"(a[2]), "r"(a[3]), "r"(b0), "r"(b1));
}
__device__ __forceinline__ void mma16816h(float c[4], const uint32_t a[4],
                                          uint32_t b0, uint32_t b1) {
    asm volatile("mma.sync.aligned.m16n8k16.row.col.f32.f16.f16.f32 "
        "{%0,%1,%2,%3}, {%4,%5,%6,%7}, {%8,%9}, {%0,%1,%2,%3};"
        : "+f"(c[0]), "+f"(c[1]), "+f"(c[2]), "+f"(c[3])
        : "r"(a[0]), "r"(a[1]), "r"(a[2]), "r"(a[3]), "r"(b0), "r"(b1));
}

// ---------------- weight conversion (once; tiny) ----------------
// z<3: bf16 hi|lo (QKV weights). z==3: fp16 hi|lo (Wo, pairs with fp16 A).
__global__ __launch_bounds__(256)
void convert_w_kernel(const float* __restrict__ ipw, const float* __restrict__ opw)
{
    const int z = blockIdx.y;
    const float* src = (z < 3) ? (ipw + (size_t)z * 65536) : opw;
    uint8_t* dst = g_wsp + (size_t)z * 262144;
    size_t g = ((size_t)blockIdx.x * 256 + threadIdx.x) * 4;
    float4 v = *(const float4*)(src + g);
    uint32_t h0,l0,h1,l1,h2,l2,h3,l3;
    if (z == 3) {
        split1h(v.x,h0,l0); split1h(v.y,h1,l1); split1h(v.z,h2,l2); split1h(v.w,h3,l3);
    } else {
        split1(v.x,h0,l0); split1(v.y,h1,l1); split1(v.z,h2,l2); split1(v.w,h3,l3);
    }
    size_t row = g >> 8;
    int c = (int)(g & 255);
    uint8_t* rp = dst + row * 1024;
    *(uint2*)(rp + 2*c)       = make_uint2(h0 | (h1<<16), h2 | (h3<<16));
    *(uint2*)(rp + 512 + 2*c) = make_uint2(l0 | (l1<<16), l2 | (l3<<16));
}

// ---------------- HMMA projection GEMM, 64m x 128n ----------------
// mode 0 (QKV): A = fp32 input, bf16 split on staging; 3-term bf16 MMA.
// mode 1 (out): A = g_ao fp16 single; W fp16 hi|lo; 2-term fp16 MMA; fp32 out.
#define PPITCH 144
#define PSM_A    0
#define PSM_W(b) (9216 + (b) * 18432)
#define SMEM_PROJ 46080

__global__ __launch_bounds__(128)
void proj_mma_kernel(const float* __restrict__ q_in, const float* __restrict__ k_in,
                     const float* __restrict__ v_in,
                     const float* __restrict__ ipb, const float* __restrict__ opb,
                     float* __restrict__ out, int mode)
{
    extern __shared__ __align__(16) uint8_t psm[];
    uint8_t* sA = psm;

    const int tid  = threadIdx.x;
    const int wid  = tid >> 5;
    const int lane = tid & 31;
    const int z = blockIdx.z;
    const int m0 = blockIdx.x * 64;
    const int n0 = blockIdx.y * 128;
    const int wm = wid >> 1;
    const int wn = wid & 1;

    const float* Af = (z == 0) ? q_in : (z == 1) ? k_in : v_in;
    const uint8_t* Wsp = g_wsp + (size_t)((mode == 0) ? z : 3) * 262144;
    const float* bias = (mode == 0) ? (ipb + z * E_DIM) : opb;
    const float scale = (mode == 0 && z == 0) ? SCALING : 1.0f;

    const uint32_t sb = smem_u32(psm);

    float acc[2][8][4];
#pragma unroll
    for (int a = 0; a < 2; a++)
#pragma unroll
        for (int t = 0; t < 8; t++)
#pragma unroll
            for (int j = 0; j < 4; j++) acc[a][t][j] = 0.f;

    // ---- prologue: async-stage W(kc=0) into buf 0 ----
    {
#pragma unroll
        for (int j = 0; j < 8; j++) {
            int i = tid + j * 128;
            int row = i >> 3, seg = i & 7;
            const uint8_t* src = Wsp + (size_t)(n0 + row) * 1024
                               + (seg < 4 ? seg * 16 : 512 + (seg - 4) * 16);
            CP16(sb + PSM_W(0) + row * PPITCH + (seg < 4 ? seg * 16 : 64 + (seg - 4) * 16),
                 src);
        }
        CP_COMMIT();
    }

    for (int kc = 0; kc < 8; kc++) {
        const int wb = kc & 1;
        __syncthreads();   // prior compute done with sA / sW[wb]
        // ---- stage A(kc) ----
        if (mode == 0) {
#pragma unroll
            for (int j = 0; j < 4; j++) {
                int i = tid + j * 128;
                int row = i >> 3, seg = i & 7;
                float4 v = *(const float4*)(Af + (size_t)(m0 + row) * E_DIM
                                            + kc * 32 + seg * 4);
                uint32_t h0,l0,h1,l1,h2,l2,h3,l3;
                split1(v.x,h0,l0); split1(v.y,h1,l1);
                split1(v.z,h2,l2); split1(v.w,h3,l3);
                *(uint2*)(sA + row * PPITCH + seg * 8) =
                    make_uint2(h0 | (h1<<16), h2 | (h3<<16));
                *(uint2*)(sA + row * PPITCH + 64 + seg * 8) =
                    make_uint2(l0 | (l1<<16), l2 | (l3<<16));
            }
        } else {
            // A = g_ao fp16 single: 64 rows x 64B per kc chunk
#pragma unroll
            for (int j = 0; j < 2; j++) {
                int i = tid + j * 128;           // 0..255
                int row = i >> 2, seg = i & 3;
                const uint8_t* src = g_ao + (size_t)(m0 + row) * 512
                                   + kc * 64 + seg * 16;
                CP16(sb + PSM_A + row * PPITCH + seg * 16, src);
            }
            CP_COMMIT();   // group: A(kc)
        }
        // ---- async-stage W(kc+1) into the other buffer ----
        if (kc + 1 < 8) {
            const int koff1 = (kc + 1) * 64;
#pragma unroll
            for (int j = 0; j < 8; j++) {
                int i = tid + j * 128;
                int row = i >> 3, seg = i & 7;
                const uint8_t* src = Wsp + (size_t)(n0 + row) * 1024
                                   + (seg < 4 ? koff1 + seg * 16 : 512 + koff1 + (seg - 4) * 16);
                CP16(sb + PSM_W(wb ^ 1) + row * PPITCH
                         + (seg < 4 ? seg * 16 : 64 + (seg - 4) * 16),
                     src);
            }
            CP_COMMIT();   // group: W(kc+1)
            CP_WAIT1();    // A(kc) [mode1] + W(kc) complete; W(kc+1) in flight
        } else {
            CP_WAIT0();
        }
        __syncthreads();

        const uint32_t sWb = sb + PSM_W(wb);
#pragma unroll
        for (int ks = 0; ks < 2; ks++) {
            uint32_t ah[2][4], al[2][4];
#pragma unroll
            for (int am = 0; am < 2; am++) {
                uint32_t aaddr = sb + PSM_A + (wm*32 + am*16 + (lane & 15)) * PPITCH
                               + ks*32 + (lane >> 4) * 16;
                LDSM4(ah[am], aaddr);
                if (mode == 0) LDSM4(al[am], aaddr + 64);
            }
            uint32_t bh[4][4], bl[4][4];
#pragma unroll
            for (int g = 0; g < 4; g++) {
                uint32_t baddr = sWb + (wn*64 + g*16 + (lane & 7) + ((lane >> 4) << 3)) * PPITCH
                               + ks*32 + ((lane >> 3) & 1) * 16;
                LDSM4(bh[g], baddr);
                LDSM4(bl[g], baddr + 64);
            }
            if (mode == 0) {
#pragma unroll
                for (int am = 0; am < 2; am++)
#pragma unroll
                    for (int g = 0; g < 4; g++) {
                        mma16816(acc[am][2*g+0], ah[am], bh[g][0], bh[g][1]);
                        mma16816(acc[am][2*g+0], ah[am], bl[g][0], bl[g][1]);
                        mma16816(acc[am][2*g+0], al[am], bh[g][0], bh[g][1]);
                        mma16816(acc[am][2*g+1], ah[am], bh[g][2], bh[g][3]);
                        mma16816(acc[am][2*g+1], ah[am], bl[g][2], bl[g][3]);
                        mma16816(acc[am][2*g+1], al[am], bh[g][2], bh[g][3]);
                    }
            } else {
#pragma unroll
                for (int am = 0; am < 2; am++)
#pragma unroll
                    for (int g = 0; g < 4; g++) {
                        mma16816h(acc[am][2*g+0], ah[am], bh[g][0], bh[g][1]);
                        mma16816h(acc[am][2*g+0], ah[am], bl[g][0], bl[g][1]);
                        mma16816h(acc[am][2*g+1], ah[am], bh[g][2], bh[g][3]);
                        mma16816h(acc[am][2*g+1], ah[am], bl[g][2], bl[g][3]);
                    }
            }
        }
    }

    const int qrow = lane >> 2, qcol = (lane & 3) << 1;
    uint8_t* dstz = (z == 0) ? g_qb : (z == 1) ? g_kb : g_vb;
#pragma unroll
    for (int am = 0; am < 2; am++) {
        const int r0 = m0 + wm*32 + am*16 + qrow;
#pragma unroll
        for (int t = 0; t < 8; t++) {
            const int e = n0 + wn*64 + (t >> 1)*16 + (t & 1)*8 + qcol;
            const float b0 = bias[e], b1 = bias[e+1];
            float v00 = (acc[am][t][0] + b0) * scale;
            float v01 = (acc[am][t][1] + b1) * scale;
            float v10 = (acc[am][t][2] + b0) * scale;
            float v11 = (acc[am][t][3] + b1) * scale;
            if (mode == 0) {
                const int hh = e >> 5, d = e & 31;
#pragma unroll
                for (int half = 0; half < 2; half++) {
                    const int r = r0 + half * 8;
                    const float va = half ? v10 : v00;
                    const float vb = half ? v11 : v01;
                    const int l = r >> 2, nn = r & 3;
                    uint8_t* rp = dstz + ((size_t)(nn * H_N + hh) * L_DIM + l) * 128;
                    uint32_t ha,la,hb,lb;
                    if (z == 2) { split1h(va, ha, la); split1h(vb, hb, lb); }
                    else        { split1(va, ha, la);  split1(vb, hb, lb); }
                    *(uint32_t*)(rp + 2*d)      = ha | (hb << 16);
                    *(uint32_t*)(rp + 64 + 2*d) = la | (lb << 16);
                }
            } else {
                *(float2*)(out + (size_t)r0 * E_DIM + e)       = make_float2(v00, v01);
                *(float2*)(out + (size_t)(r0+8) * E_DIM + e)   = make_float2(v10, v11);
            }
        }
    }
}

// ---------------- Attention: HMMA flash v4 (R13 core; fp16 g_ao epilogue) ----------------
#define KV_PITCH  144
#define REL_PITCH 36
#define SM_K(b)   ((b) * 4608)
#define SM_V(b)   (9216 + (b) * 4608)
#define SM_REL(b) (18432 + (b) * 18432)
#define SMEM_ATTN 55296

__global__ void __launch_bounds__(128, 4) attn_mma_kernel(const float* __restrict__ rel)
{
    extern __shared__ __align__(16) uint8_t smem[];
    const int tid  = threadIdx.x;
    const int wid  = tid >> 5;
    const int lane = tid & 31;
    const int bh = blockIdx.y;
    const int l0 = blockIdx.x * 128;
    const int WROW = wid * 32;

    const uint32_t sb = smem_u32(smem);
    const uint4* ksrc = (const uint4*)(g_kb + (size_t)bh * S_DIM * 128);
    const uint4* vsrc = (const uint4*)(g_vb + (size_t)bh * S_DIM * 128);
    const float* relg = rel + ((size_t)bh * L_DIM + l0) * S_DIM;

    {
        const uint4* qs = (const uint4*)(g_qb + ((size_t)bh * L_DIM + l0) * 128);
        uint32_t qb = sb + SM_REL(0);
#pragma unroll
        for (int j = 0; j < 8; j++) {
            int i = tid + j * 128;
            CP16(qb + (i >> 3) * KV_PITCH + (i & 7) * 16, qs + i);
        }
        CP_COMMIT(); CP_WAIT0();
    }
    __syncthreads();
    uint32_t qh0[2][4], qh1[2][4], ql0[2][4], ql1[2][4];
#pragma unroll
    for (int am = 0; am < 2; am++) {
        uint32_t qaddr = sb + SM_REL(0) + (WROW + 16*am + (lane & 15)) * KV_PITCH
                       + (lane >> 4) * 16;
        LDSM4(qh0[am], qaddr);
        LDSM4(qh1[am], qaddr + 32);
        LDSM4(ql0[am], qaddr + 64);
        LDSM4(ql1[am], qaddr + 96);
    }
    __syncthreads();

    {
#pragma unroll
        for (int j = 0; j < 2; j++) {
            int i = tid + j * 128;
            uint32_t o = (i >> 3) * KV_PITCH + (i & 7) * 16;
            CP16(sb + SM_K(0) + o, ksrc + i);
            CP16(sb + SM_V(0) + o, vsrc + i);
        }
#pragma unroll
        for (int j = 0; j < 8; j++) {
            int i = tid + j * 128;
            int row = i >> 3, seg = i & 7;
            CP16(sb + SM_REL(0) + row * (REL_PITCH * 4) + seg * 16,
                 (const uint4*)(relg + (size_t)row * S_DIM) + seg);
        }
        CP_COMMIT();
    }

    float O[2][4][4];
#pragma unroll
    for (int am = 0; am < 2; am++)
#pragma unroll
        for (int t = 0; t < 4; t++)
#pragma unroll
            for (int j = 0; j < 4; j++) O[am][t][j] = 0.f;
    float rs[2][2] = {{0.f, 0.f}, {0.f, 0.f}};

    const int qrow = lane >> 2;
    const int qcol = (lane & 3) << 1;

    for (int c = 0; c < S_DIM / 32; ++c) {
        const int cur = c & 1;
        if (c + 1 < S_DIM / 32) {
            const int nxt = cur ^ 1;
            const int s1 = (c + 1) * 32;
#pragma unroll
            for (int j = 0; j < 2; j++) {
                int i = tid + j * 128;
                uint32_t o = (i >> 3) * KV_PITCH + (i & 7) * 16;
                CP16(sb + SM_K(nxt) + o, ksrc + (c + 1) * 256 + i);
                CP16(sb + SM_V(nxt) + o, vsrc + (c + 1) * 256 + i);
            }
#pragma unroll
            for (int j = 0; j < 8; j++) {
                int i = tid + j * 128;
                int row = i >> 3, seg = i & 7;
                CP16(sb + SM_REL(nxt) + row * (REL_PITCH * 4) + seg * 16,
                     (const uint4*)(relg + (size_t)row * S_DIM + s1) + seg);
            }
            CP_COMMIT();
            CP_WAIT1();
        } else {
            CP_WAIT0();
        }
        __syncthreads();

        const float* srel = (const float*)(smem + SM_REL(cur));
        const uint32_t skb = sb + SM_K(cur), svb = sb + SM_V(cur);

#pragma unroll
        for (int np = 0; np < 2; np++) {
            uint32_t kaddr = skb + (16*np + (lane & 7) + ((lane >> 4) << 3)) * KV_PITCH
                           + ((lane >> 3) & 1) * 16;
            uint32_t kh0[4], kh1[4], kl0[4], kl1[4];
            LDSM4(kh0, kaddr);
            LDSM4(kh1, kaddr + 32);
            LDSM4(kl0, kaddr + 64);
            LDSM4(kl1, kaddr + 96);
            uint32_t vaddr = svb + (16*np + (lane & 15)) * KV_PITCH + (lane >> 4) * 16;
            uint32_t vh0[4], vh1[4], vl0[4], vl1[4];
            LDSM4T(vh0, vaddr);
            LDSM4T(vh1, vaddr + 32);
            LDSM4T(vl0, vaddr + 64);
            LDSM4T(vl1, vaddr + 96);

#pragma unroll
            for (int am = 0; am < 2; am++) {
                const float* r0 = srel + (WROW + 16*am + qrow) * REL_PITCH + 16*np + qcol;
                float cA[4], cB[4];
                {
                    float2 t0 = *(const float2*)(r0);
                    float2 t1 = *(const float2*)(r0 + 8 * REL_PITCH);
                    float2 t2 = *(const float2*)(r0 + 8);
                    float2 t3 = *(const float2*)(r0 + 8 * REL_PITCH + 8);
                    cA[0]=t0.x; cA[1]=t0.y; cA[2]=t1.x; cA[3]=t1.y;
                    cB[0]=t2.x; cB[1]=t2.y; cB[2]=t3.x; cB[3]=t3.y;
                }
                mma16816(cA, qh0[am], kh0[0], kh0[1]);
                mma16816(cA, qh1[am], kh1[0], kh1[1]);
                mma16816(cA, qh0[am], kl0[0], kl0[1]);
                mma16816(cA, qh1[am], kl1[0], kl1[1]);
                mma16816(cA, ql0[am], kh0[0], kh0[1]);
                mma16816(cA, ql1[am], kh1[0], kh1[1]);

                mma16816(cB, qh0[am], kh0[2], kh0[3]);
                mma16816(cB, qh1[am], kh1[2], kh1[3]);
                mma16816(cB, qh0[am], kl0[2], kl0[3]);
                mma16816(cB, qh1[am], kl1[2], kl1[3]);
                mma16816(cB, ql0[am], kh0[2], kh0[3]);
                mma16816(cB, ql1[am], kh1[2], kh1[3]);

                float pA0 = __expf(cA[0]), pA1 = __expf(cA[1]);
                float pA2 = __expf(cA[2]), pA3 = __expf(cA[3]);
                float pB0 = __expf(cB[0]), pB1 = __expf(cB[1]);
                float pB2 = __expf(cB[2]), pB3 = __expf(cB[3]);
                rs[am][0] += (pA0 + pA1) + (pB0 + pB1);
                rs[am][1] += (pA2 + pA3) + (pB2 + pB3);

                uint32_t phi[4];
                phi[0] = packh2(pA0, pA1); phi[1] = packh2(pA2, pA3);
                phi[2] = packh2(pB0, pB1); phi[3] = packh2(pB2, pB3);

                mma16816h(O[am][0], phi, vh0[0], vh0[1]);
                mma16816h(O[am][0], phi, vl0[0], vl0[1]);

                mma16816h(O[am][1], phi, vh0[2], vh0[3]);
                mma16816h(O[am][1], phi, vl0[2], vl0[3]);

                mma16816h(O[am][2], phi, vh1[0], vh1[1]);
                mma16816h(O[am][2], phi, vl1[0], vl1[1]);

                mma16816h(O[am][3], phi, vh1[2], vh1[3]);
                mma16816h(O[am][3], phi, vl1[2], vl1[3]);
            }
        }
        __syncthreads();
    }

    // ---- epilogue: normalize, fp16 single into g_ao (512B rows) ----
    const int n = bh >> 3, h = bh & 7;
#pragma unroll
    for (int am = 0; am < 2; am++) {
        float s0 = rs[am][0], s1 = rs[am][1];
        s0 += __shfl_xor_sync(0xffffffffu, s0, 1);
        s0 += __shfl_xor_sync(0xffffffffu, s0, 2);
        s1 += __shfl_xor_sync(0xffffffffu, s1, 1);
        s1 += __shfl_xor_sync(0xffffffffu, s1, 2);
        const float inv0 = 1.0f / s0, inv1 = 1.0f / s1;

        const int r = l0 + WROW + 16*am + qrow;
        uint8_t* rp0 = g_ao + ((size_t)r * N_B + n) * 512;
        uint8_t* rp8 = rp0 + (size_t)8 * N_B * 512;
#pragma unroll
        for (int t = 0; t < 4; t++) {
            const int e = h * HD_N + t * 8 + qcol;
            *(uint32_t*)(rp0 + 2*e) = packh2(O[am][t][0] * inv0, O[am][t][1] * inv0);
            *(uint32_t*)(rp8 + 2*e) = packh2(O[am][t][2] * inv1, O[am][t][3] * inv1);
        }
    }
}

// ---------------------------------------------------------------------------
extern "C" void kernel_launch(void* const* d_in, const int* in_sizes, int n_in,
                              void* d_out, int out_size)
{
    const float* query = (const float*)d_in[0];
    const float* key   = (const float*)d_in[1];
    const float* value = (const float*)d_in[2];
    const float* rel   = (const float*)d_in[3];
    const float* ipw   = (const float*)d_in[4];
    const float* ipb   = (const float*)d_in[5];
    const float* opw   = (const float*)d_in[6];
    const float* opb   = (const float*)d_in[7];
    float* out = (float*)d_out;

    cudaFuncSetAttribute(attn_mma_kernel,
                         cudaFuncAttributeMaxDynamicSharedMemorySize, SMEM_ATTN);
    cudaFuncSetAttribute(proj_mma_kernel,
                         cudaFuncAttributeMaxDynamicSharedMemorySize, SMEM_PROJ);

    convert_w_kernel<<<dim3(64, 4), 256>>>(ipw, opw);

    proj_mma_kernel<<<dim3(128, 2, 3), 128, SMEM_PROJ>>>(query, key, value,
                                                         ipb, opb, out, 0);

    attn_mma_kernel<<<dim3(16, 32), 128, SMEM_ATTN>>>(rel);

    proj_mma_kernel<<<dim3(128, 2, 1), 128, SMEM_PROJ>>>(query, key, value,
                                                         ipb, opb, out, 1);
}